// round 9
// baseline (speedup 1.0000x reference)
#include <cuda_runtime.h>
#include <math.h>

#define POOLN 7
#define NROIS 4
#define FEAT 2048
#define RED 512
#define FLATN (RED * 49)      // 25088 = 14 * 1792
#define H1N 4096
#define H2N 2048
#define NCLS 21
#define NREG 80
#define IMG 128

#define D1_CHUNK 1792
#define D1_KSPLIT 14          // 14 splits * 1792 = 25088

// packed f32x2 helpers (FFMA2 path — PTX-only)
#define PACK2(u, a, b) asm("mov.b64 %0, {%1, %2};" : "=l"(u) : "f"(a), "f"(b))
#define FMA2(acc, u, v) \
    asm("fma.rn.f32x2 %0, %1, %2, %0;" : "+l"(acc) : "l"(u), "l"(v))
#define UNPACK2(a, b, u) asm("mov.b64 {%0, %1}, %2;" : "=f"(a), "=f"(b) : "l"(u))

// ---------------- scratch (device globals; no allocations allowed) -------
__device__ float g_pooled[NROIS * 49 * FEAT];   // [r*49+hw][c]  c fastest
__device__ float g_flat[NROIS * FLATN];         // [r][o*49 + hw], bias-seeded
__device__ float g_h1[NROIS * H1N];             // pre-relu, bias-seeded
__device__ float g_h2[NROIS * H2N];             // pre-relu, bias-seeded
__device__ float g_logits[NROIS * NCLS];

__device__ __forceinline__ float wsum(float v) {
#pragma unroll
    for (int o = 16; o > 0; o >>= 1) v += __shfl_xor_sync(0xffffffffu, v, o);
    return v;
}

// ---------------- kernel 1: ROI adaptive avg pool (R5) + g_flat seed ------
// 4 channels / block, float4 column loads. grid = 4r * 512 = 2048 blocks.
__global__ __launch_bounds__(224) void pool_kernel(
    const float* __restrict__ x, const int* __restrict__ rois,
    const float* __restrict__ conv_b) {
    // prologue: seed g_flat with conv bias (conv accumulates via atomics)
    {
        int gid = blockIdx.x * 224 + threadIdx.x;
        if (gid < NROIS * FLATN) {
            int rem = gid % FLATN;
            g_flat[gid] = conv_b[rem / 49];
        }
    }

    int blk = blockIdx.x;
    int r = blk & 3;
    int c0 = (blk >> 2) * 4;
    int wid = threadIdx.x >> 5;
    int lane = threadIdx.x & 31;

    int x0 = rois[r * 4 + 0];
    int y0 = rois[r * 4 + 1];
    int Wc = rois[r * 4 + 2];   // cols count (axis2 = y:y+h)
    int Hc = rois[r * 4 + 3];   // rows count (axis1 = x:x+w)

    int ph = wid;
    int hs = (ph * Hc) / 7;
    int he = ((ph + 1) * Hc + 6) / 7;

    int ya = y0 & ~3;
    int nl = (y0 + Wc - ya + 3) >> 2;
    int nlmax = (IMG - ya) >> 2;
    if (nl > nlmax) nl = nlmax;

    float4 s0 = {0,0,0,0}, s1 = {0,0,0,0}, s2 = {0,0,0,0}, s3 = {0,0,0,0};

    if (lane < nl) {
        const float* pl0 = x + (size_t)(c0 + 0) * (IMG * IMG) +
                           (size_t)x0 * IMG + ya + 4 * lane;
        const float* pl1 = pl0 + IMG * IMG;
        const float* pl2 = pl1 + IMG * IMG;
        const float* pl3 = pl2 + IMG * IMG;
        int a = hs;
        for (; a + 1 < he; a += 2) {
            float4 v00 = *(const float4*)(pl0 + (a + 0) * IMG);
            float4 v10 = *(const float4*)(pl1 + (a + 0) * IMG);
            float4 v20 = *(const float4*)(pl2 + (a + 0) * IMG);
            float4 v30 = *(const float4*)(pl3 + (a + 0) * IMG);
            float4 v01 = *(const float4*)(pl0 + (a + 1) * IMG);
            float4 v11 = *(const float4*)(pl1 + (a + 1) * IMG);
            float4 v21 = *(const float4*)(pl2 + (a + 1) * IMG);
            float4 v31 = *(const float4*)(pl3 + (a + 1) * IMG);
            s0.x += v00.x + v01.x; s0.y += v00.y + v01.y;
            s0.z += v00.z + v01.z; s0.w += v00.w + v01.w;
            s1.x += v10.x + v11.x; s1.y += v10.y + v11.y;
            s1.z += v10.z + v11.z; s1.w += v10.w + v11.w;
            s2.x += v20.x + v21.x; s2.y += v20.y + v21.y;
            s2.z += v20.z + v21.z; s2.w += v20.w + v21.w;
            s3.x += v30.x + v31.x; s3.y += v30.y + v31.y;
            s3.z += v30.z + v31.z; s3.w += v30.w + v31.w;
        }
        if (a < he) {
            float4 v0 = *(const float4*)(pl0 + a * IMG);
            float4 v1 = *(const float4*)(pl1 + a * IMG);
            float4 v2 = *(const float4*)(pl2 + a * IMG);
            float4 v3 = *(const float4*)(pl3 + a * IMG);
            s0.x += v0.x; s0.y += v0.y; s0.z += v0.z; s0.w += v0.w;
            s1.x += v1.x; s1.y += v1.y; s1.z += v1.z; s1.w += v1.w;
            s2.x += v2.x; s2.y += v2.y; s2.z += v2.z; s2.w += v2.w;
            s3.x += v3.x; s3.y += v3.y; s3.z += v3.z; s3.w += v3.w;
        }
    }

    float acc[4][7];
#pragma unroll
    for (int cc = 0; cc < 4; cc++)
#pragma unroll
        for (int pw = 0; pw < 7; pw++) acc[cc][pw] = 0.f;

    float sc[4][4] = {{s0.x, s0.y, s0.z, s0.w}, {s1.x, s1.y, s1.z, s1.w},
                      {s2.x, s2.y, s2.z, s2.w}, {s3.x, s3.y, s3.z, s3.w}};
#pragma unroll
    for (int q = 0; q < 4; q++) {
        int b = ya + 4 * lane + q - y0;
        bool valid = (b >= 0) && (b < Wc);
#pragma unroll
        for (int pw = 0; pw < 7; pw++) {
            int ws = (pw * Wc) / 7;
            int we = ((pw + 1) * Wc + 6) / 7;
            if (valid && b >= ws && b < we) {
#pragma unroll
                for (int cc = 0; cc < 4; cc++) acc[cc][pw] += sc[cc][q];
            }
        }
    }

#pragma unroll
    for (int pw = 0; pw < 7; pw++) {
        float v0 = wsum(acc[0][pw]);
        float v1 = wsum(acc[1][pw]);
        float v2 = wsum(acc[2][pw]);
        float v3 = wsum(acc[3][pw]);
        if (lane == 0) {
            int ws = (pw * Wc) / 7;
            int we = ((pw + 1) * Wc + 6) / 7;
            float inv = 1.f / (float)((he - hs) * (we - ws));
            int ob = ((r * 7 + ph) * 7 + pw) * FEAT + c0;
            g_pooled[ob + 0] = v0 * inv;
            g_pooled[ob + 1] = v1 * inv;
            g_pooled[ob + 2] = v2 * inv;
            g_pooled[ob + 3] = v3 * inv;
        }
    }
}

// ---------------- kernel 2: 1x1 conv, thread-parallel ---------------------
// grid = 8 osplit * 7 ph * 8 ksplit = 448 blocks; 256 threads = 64 o x 4 r.
// Each thread: 7 accumulators (one per pw), K chunk of 256 via 28KB smem.
// No warp reductions; partials atomicAdd into bias-seeded g_flat.
// Per-block L2: 28KB act + 64KB weights (total ~12.5MB + 28MB vs 100MB before).
__global__ __launch_bounds__(256) void conv_kernel(
    const float* __restrict__ conv_w,
    const float* __restrict__ d1_b, const float* __restrict__ d2_b) {
    __shared__ float smact[4 * 7 * 256];   // 28 KB  [r][pw][k]

    // seed g_h1/g_h2 with biases (d1/d2 accumulate via atomics later)
    {
        int gi = blockIdx.x * 256 + threadIdx.x;
        if (gi < H1N) {
            float b = d1_b[gi];
#pragma unroll
            for (int rr = 0; rr < 4; rr++) g_h1[rr * H1N + gi] = b;
        } else if (gi < H1N + H2N) {
            int j = gi - H1N;
            float b = d2_b[j];
#pragma unroll
            for (int rr = 0; rr < 4; rr++) g_h2[rr * H2N + j] = b;
        }
    }

    int b = blockIdx.x;
    int ks = b & 7;
    int rest = b >> 3;          // 0..55
    int ph = rest % 7;
    int osplit = rest / 7;      // 0..7
    int kb = ks * 256;
    int tid = threadIdx.x;
    int o = osplit * 64 + (tid >> 2);
    int rr = tid & 3;

    // fill act chunk: [4r][7pw][256k] from g_pooled
    for (int i = tid; i < 1792; i += 256) {
        int r4 = i / 448;
        int rem = i - r4 * 448;
        int pw = rem / 64;
        int k4 = rem - pw * 64;
        *(float4*)(smact + (r4 * 7 + pw) * 256 + k4 * 4) =
            *(const float4*)(g_pooled + (size_t)((r4 * 7 + ph) * 7 + pw) * FEAT +
                             kb + k4 * 4);
    }
    __syncthreads();

    float acc[7];
#pragma unroll
    for (int pw = 0; pw < 7; pw++) acc[pw] = 0.f;

    const float4* wp = (const float4*)(conv_w + (size_t)o * FEAT + kb);
    const float* ab = smact + rr * 7 * 256;
#pragma unroll 4
    for (int k4 = 0; k4 < 64; k4++) {
        float4 w = wp[k4];
#pragma unroll
        for (int pw = 0; pw < 7; pw++) {
            float4 f = *(const float4*)(ab + pw * 256 + k4 * 4);
            acc[pw] += w.x * f.x + w.y * f.y + w.z * f.z + w.w * f.w;
        }
    }

    float* dst = g_flat + (size_t)rr * FLATN + o * 49 + ph * 7;
#pragma unroll
    for (int pw = 0; pw < 7; pw++) atomicAdd(&dst[pw], acc[pw]);
}

// ---------------- kernel 3: dense1 (R5 exact: f32x2, 2 rows, 3584 blk) ----
__global__ __launch_bounds__(256) void d1_kernel(const float* __restrict__ d1_w) {
    __shared__ float smf[4 * D1_CHUNK];   // 28 KB
    int ks = blockIdx.x % D1_KSPLIT;
    int rowblk = blockIdx.x / D1_KSPLIT;
    int wid = threadIdx.x >> 5;
    int lane = threadIdx.x & 31;
    int j0 = rowblk * 16 + wid * 2;
    int kb = ks * D1_CHUNK;

    for (int i = threadIdx.x; i < 1792; i += 256) {
        int rr = i / 448;
        int k4 = i - rr * 448;
        *(float4*)(smf + rr * D1_CHUNK + k4 * 4) =
            *(const float4*)(g_flat + (size_t)rr * FLATN + kb + k4 * 4);
    }
    __syncthreads();

    unsigned long long a00 = 0, a01 = 0, a02 = 0, a03 = 0;
    unsigned long long a10 = 0, a11 = 0, a12 = 0, a13 = 0;

    const float* wp0 = d1_w + (size_t)(j0 + 0) * FLATN + kb;
    const float* wp1 = d1_w + (size_t)(j0 + 1) * FLATN + kb;
#pragma unroll
    for (int it = 0; it < 14; it++) {
        int k = lane * 4 + it * 128;
        float4 w0 = __ldcs((const float4*)(wp0 + k));
        float4 w1 = __ldcs((const float4*)(wp1 + k));
        unsigned long long w0lo, w0hi, w1lo, w1hi;
        PACK2(w0lo, w0.x, w0.y); PACK2(w0hi, w0.z, w0.w);
        PACK2(w1lo, w1.x, w1.y); PACK2(w1hi, w1.z, w1.w);
        ulonglong2 f0 = *(const ulonglong2*)(smf + 0 * D1_CHUNK + k);
        ulonglong2 f1 = *(const ulonglong2*)(smf + 1 * D1_CHUNK + k);
        ulonglong2 f2 = *(const ulonglong2*)(smf + 2 * D1_CHUNK + k);
        ulonglong2 f3 = *(const ulonglong2*)(smf + 3 * D1_CHUNK + k);
        FMA2(a00, w0lo, f0.x); FMA2(a00, w0hi, f0.y);
        FMA2(a01, w0lo, f1.x); FMA2(a01, w0hi, f1.y);
        FMA2(a02, w0lo, f2.x); FMA2(a02, w0hi, f2.y);
        FMA2(a03, w0lo, f3.x); FMA2(a03, w0hi, f3.y);
        FMA2(a10, w1lo, f0.x); FMA2(a10, w1hi, f0.y);
        FMA2(a11, w1lo, f1.x); FMA2(a11, w1hi, f1.y);
        FMA2(a12, w1lo, f2.x); FMA2(a12, w1hi, f2.y);
        FMA2(a13, w1lo, f3.x); FMA2(a13, w1hi, f3.y);
    }

    float lo, hi, r00, r01, r02, r03, r10, r11, r12, r13;
    UNPACK2(lo, hi, a00); r00 = wsum(lo + hi);
    UNPACK2(lo, hi, a01); r01 = wsum(lo + hi);
    UNPACK2(lo, hi, a02); r02 = wsum(lo + hi);
    UNPACK2(lo, hi, a03); r03 = wsum(lo + hi);
    UNPACK2(lo, hi, a10); r10 = wsum(lo + hi);
    UNPACK2(lo, hi, a11); r11 = wsum(lo + hi);
    UNPACK2(lo, hi, a12); r12 = wsum(lo + hi);
    UNPACK2(lo, hi, a13); r13 = wsum(lo + hi);
    if (lane == 0) {
        atomicAdd(&g_h1[0 * H1N + j0 + 0], r00);
        atomicAdd(&g_h1[1 * H1N + j0 + 0], r01);
        atomicAdd(&g_h1[2 * H1N + j0 + 0], r02);
        atomicAdd(&g_h1[3 * H1N + j0 + 0], r03);
        atomicAdd(&g_h1[0 * H1N + j0 + 1], r10);
        atomicAdd(&g_h1[1 * H1N + j0 + 1], r11);
        atomicAdd(&g_h1[2 * H1N + j0 + 1], r12);
        atomicAdd(&g_h1[3 * H1N + j0 + 1], r13);
    }
}

// ---------------- kernel 4: dense2 (R5 exact: K-split 8, 1024 blocks) -----
__global__ __launch_bounds__(256) void d2_kernel(const float* __restrict__ d2_w) {
    __shared__ float smh[4 * 512];   // 8 KB
    int ks = blockIdx.x & 7;
    int rowblk = blockIdx.x >> 3;
    int wid = threadIdx.x >> 5;
    int lane = threadIdx.x & 31;
    int j0 = rowblk * 16 + wid * 2;
    int kb = ks * 512;

    for (int i = threadIdx.x; i < 512; i += 256) {   // float4 units
        int rr = i >> 7;
        int k4 = i & 127;
        float4 v = *(const float4*)(g_h1 + (size_t)rr * H1N + kb + k4 * 4);
        v.x = fmaxf(v.x, 0.f); v.y = fmaxf(v.y, 0.f);
        v.z = fmaxf(v.z, 0.f); v.w = fmaxf(v.w, 0.f);
        *(float4*)(smh + rr * 512 + k4 * 4) = v;
    }
    __syncthreads();

    unsigned long long a00 = 0, a01 = 0, a02 = 0, a03 = 0;
    unsigned long long a10 = 0, a11 = 0, a12 = 0, a13 = 0;

    const float* wp0 = d2_w + (size_t)(j0 + 0) * H1N + kb;
    const float* wp1 = d2_w + (size_t)(j0 + 1) * H1N + kb;
#pragma unroll
    for (int it = 0; it < 4; it++) {
        int k = lane * 4 + it * 128;
        float4 w0 = __ldcs((const float4*)(wp0 + k));
        float4 w1 = __ldcs((const float4*)(wp1 + k));
        unsigned long long w0lo, w0hi, w1lo, w1hi;
        PACK2(w0lo, w0.x, w0.y); PACK2(w0hi, w0.z, w0.w);
        PACK2(w1lo, w1.x, w1.y); PACK2(w1hi, w1.z, w1.w);
        ulonglong2 f0 = *(const ulonglong2*)(smh + 0 * 512 + k);
        ulonglong2 f1 = *(const ulonglong2*)(smh + 1 * 512 + k);
        ulonglong2 f2 = *(const ulonglong2*)(smh + 2 * 512 + k);
        ulonglong2 f3 = *(const ulonglong2*)(smh + 3 * 512 + k);
        FMA2(a00, w0lo, f0.x); FMA2(a00, w0hi, f0.y);
        FMA2(a01, w0lo, f1.x); FMA2(a01, w0hi, f1.y);
        FMA2(a02, w0lo, f2.x); FMA2(a02, w0hi, f2.y);
        FMA2(a03, w0lo, f3.x); FMA2(a03, w0hi, f3.y);
        FMA2(a10, w1lo, f0.x); FMA2(a10, w1hi, f0.y);
        FMA2(a11, w1lo, f1.x); FMA2(a11, w1hi, f1.y);
        FMA2(a12, w1lo, f2.x); FMA2(a12, w1hi, f2.y);
        FMA2(a13, w1lo, f3.x); FMA2(a13, w1hi, f3.y);
    }

    float lo, hi, r00, r01, r02, r03, r10, r11, r12, r13;
    UNPACK2(lo, hi, a00); r00 = wsum(lo + hi);
    UNPACK2(lo, hi, a01); r01 = wsum(lo + hi);
    UNPACK2(lo, hi, a02); r02 = wsum(lo + hi);
    UNPACK2(lo, hi, a03); r03 = wsum(lo + hi);
    UNPACK2(lo, hi, a10); r10 = wsum(lo + hi);
    UNPACK2(lo, hi, a11); r11 = wsum(lo + hi);
    UNPACK2(lo, hi, a12); r12 = wsum(lo + hi);
    UNPACK2(lo, hi, a13); r13 = wsum(lo + hi);
    if (lane == 0) {
        atomicAdd(&g_h2[0 * H2N + j0 + 0], r00);
        atomicAdd(&g_h2[1 * H2N + j0 + 0], r01);
        atomicAdd(&g_h2[2 * H2N + j0 + 0], r02);
        atomicAdd(&g_h2[3 * H2N + j0 + 0], r03);
        atomicAdd(&g_h2[0 * H2N + j0 + 1], r10);
        atomicAdd(&g_h2[1 * H2N + j0 + 1], r11);
        atomicAdd(&g_h2[2 * H2N + j0 + 1], r12);
        atomicAdd(&g_h2[3 * H2N + j0 + 1], r13);
    }
}

// ---------------- kernel 5: heads (52 blocks, R5 exact) --------------------
// grid = 4 r * 13 rowgroups; 8 warps, one output row each (101 rows total).
__global__ __launch_bounds__(256) void head_kernel(
    const float* __restrict__ d3_w, const float* __restrict__ d4_w,
    float* __restrict__ out) {
    __shared__ float smh[H2N];
    int r = blockIdx.x & 3;
    int grp = blockIdx.x >> 2;
    int wid = threadIdx.x >> 5;
    int lane = threadIdx.x & 31;

    for (int i = threadIdx.x; i < H2N / 4; i += 256) {
        float4 v = *(const float4*)(g_h2 + (size_t)r * H2N + i * 4);
        v.x = fmaxf(v.x, 0.f); v.y = fmaxf(v.y, 0.f);
        v.z = fmaxf(v.z, 0.f); v.w = fmaxf(v.w, 0.f);
        *(float4*)(smh + i * 4) = v;
    }
    __syncthreads();

    int row = grp * 8 + wid;
    if (row >= NCLS + NREG) return;
    const float* wrow = (row < NCLS)
                            ? d3_w + (size_t)row * H2N
                            : d4_w + (size_t)(row - NCLS) * H2N;
    float a = 0.f;
#pragma unroll
    for (int it = 0; it < 16; it++) {
        int k = lane * 4 + it * 128;
        float4 w = __ldcs((const float4*)(wrow + k));
        float4 f = *(const float4*)(smh + k);
        a += w.x * f.x + w.y * f.y + w.z * f.z + w.w * f.w;
    }
    a = wsum(a);
    if (lane == 0) {
        if (row < NCLS) g_logits[r * NCLS + row] = a;
        else out[NROIS * NCLS + r * NREG + (row - NCLS)] = a;
    }
}

// ---------------- kernel 6: softmax over class logits (R5 exact) -----------
__global__ __launch_bounds__(128) void softmax_kernel(float* __restrict__ out) {
    int r = threadIdx.x >> 5;
    int lane = threadIdx.x & 31;
    float v = (lane < NCLS) ? g_logits[r * NCLS + lane] : -INFINITY;
    float m = v;
#pragma unroll
    for (int o = 16; o > 0; o >>= 1)
        m = fmaxf(m, __shfl_xor_sync(0xffffffffu, m, o));
    float e = (lane < NCLS) ? expf(v - m) : 0.f;
    float s = wsum(e);
    if (lane < NCLS) out[r * NCLS + lane] = e / s;
}

// ---------------- launch ---------------------------------------------------
extern "C" void kernel_launch(void* const* d_in, const int* in_sizes, int n_in,
                              void* d_out, int out_size) {
    const float* base_x = (const float*)d_in[0];
    const int*   rois   = (const int*)d_in[1];
    const float* conv_w = (const float*)d_in[2];
    const float* conv_b = (const float*)d_in[3];
    const float* d1_w   = (const float*)d_in[4];
    const float* d1_b   = (const float*)d_in[5];
    const float* d2_w   = (const float*)d_in[6];
    const float* d2_b   = (const float*)d_in[7];
    const float* d3_w   = (const float*)d_in[8];
    const float* d4_w   = (const float*)d_in[9];
    float* out = (float*)d_out;

    pool_kernel<<<NROIS * (FEAT / 4), 224>>>(base_x, rois, conv_b);
    conv_kernel<<<448, 256>>>(conv_w, d1_b, d2_b);
    d1_kernel<<<256 * D1_KSPLIT, 256>>>(d1_w);
    d2_kernel<<<1024, 256>>>(d2_w);
    head_kernel<<<52, 256>>>(d3_w, d4_w, out);
    softmax_kernel<<<1, 128>>>(out);
}

// round 11
// speedup vs baseline: 1.1969x; 1.1969x over previous
#include <cuda_runtime.h>
#include <math.h>

#define POOLN 7
#define NROIS 4
#define FEAT 2048
#define RED 512
#define FLATN (RED * 49)      // 25088 = 28 * 896
#define H1N 4096
#define H2N 2048
#define NCLS 21
#define NREG 80
#define IMG 128

#define D1_CHUNK 896
#define D1_KSPLIT 28          // 28 splits * 896 = 25088

// packed f32x2 helpers (FFMA2 path — PTX-only)
#define PACK2(u, a, b) asm("mov.b64 %0, {%1, %2};" : "=l"(u) : "f"(a), "f"(b))
#define FMA2(acc, u, v) \
    asm("fma.rn.f32x2 %0, %1, %2, %0;" : "+l"(acc) : "l"(u), "l"(v))
#define UNPACK2(a, b, u) asm("mov.b64 {%0, %1}, %2;" : "=f"(a), "=f"(b) : "l"(u))

// ---------------- scratch (device globals; no allocations allowed) -------
__device__ float g_pooled[NROIS * 49 * FEAT];   // [r*49+hw][c]  c fastest
__device__ float g_flat[NROIS * FLATN];         // [r][o*49 + hw]
__device__ float g_h1[NROIS * H1N];             // pre-relu, bias-seeded
__device__ float g_h2[NROIS * H2N];             // pre-relu, bias-seeded
__device__ float g_logits[NROIS * NCLS];

__device__ __forceinline__ float wsum(float v) {
#pragma unroll
    for (int o = 16; o > 0; o >>= 1) v += __shfl_xor_sync(0xffffffffu, v, o);
    return v;
}

// ---------------- kernel 1: ROI adaptive avg pool (R5 exact) --------------
// 4 channels / block, float4 column loads. grid = 4r * 512 = 2048 blocks.
__global__ __launch_bounds__(224) void pool_kernel(
    const float* __restrict__ x, const int* __restrict__ rois) {
    int blk = blockIdx.x;
    int r = blk & 3;
    int c0 = (blk >> 2) * 4;
    int wid = threadIdx.x >> 5;
    int lane = threadIdx.x & 31;

    int x0 = rois[r * 4 + 0];
    int y0 = rois[r * 4 + 1];
    int Wc = rois[r * 4 + 2];   // cols count (axis2 = y:y+h)
    int Hc = rois[r * 4 + 3];   // rows count (axis1 = x:x+w)

    int ph = wid;
    int hs = (ph * Hc) / 7;
    int he = ((ph + 1) * Hc + 6) / 7;

    int ya = y0 & ~3;
    int nl = (y0 + Wc - ya + 3) >> 2;
    int nlmax = (IMG - ya) >> 2;
    if (nl > nlmax) nl = nlmax;

    float4 s0 = {0,0,0,0}, s1 = {0,0,0,0}, s2 = {0,0,0,0}, s3 = {0,0,0,0};

    if (lane < nl) {
        const float* pl0 = x + (size_t)(c0 + 0) * (IMG * IMG) +
                           (size_t)x0 * IMG + ya + 4 * lane;
        const float* pl1 = pl0 + IMG * IMG;
        const float* pl2 = pl1 + IMG * IMG;
        const float* pl3 = pl2 + IMG * IMG;
        int a = hs;
        for (; a + 1 < he; a += 2) {
            float4 v00 = *(const float4*)(pl0 + (a + 0) * IMG);
            float4 v10 = *(const float4*)(pl1 + (a + 0) * IMG);
            float4 v20 = *(const float4*)(pl2 + (a + 0) * IMG);
            float4 v30 = *(const float4*)(pl3 + (a + 0) * IMG);
            float4 v01 = *(const float4*)(pl0 + (a + 1) * IMG);
            float4 v11 = *(const float4*)(pl1 + (a + 1) * IMG);
            float4 v21 = *(const float4*)(pl2 + (a + 1) * IMG);
            float4 v31 = *(const float4*)(pl3 + (a + 1) * IMG);
            s0.x += v00.x + v01.x; s0.y += v00.y + v01.y;
            s0.z += v00.z + v01.z; s0.w += v00.w + v01.w;
            s1.x += v10.x + v11.x; s1.y += v10.y + v11.y;
            s1.z += v10.z + v11.z; s1.w += v10.w + v11.w;
            s2.x += v20.x + v21.x; s2.y += v20.y + v21.y;
            s2.z += v20.z + v21.z; s2.w += v20.w + v21.w;
            s3.x += v30.x + v31.x; s3.y += v30.y + v31.y;
            s3.z += v30.z + v31.z; s3.w += v30.w + v31.w;
        }
        if (a < he) {
            float4 v0 = *(const float4*)(pl0 + a * IMG);
            float4 v1 = *(const float4*)(pl1 + a * IMG);
            float4 v2 = *(const float4*)(pl2 + a * IMG);
            float4 v3 = *(const float4*)(pl3 + a * IMG);
            s0.x += v0.x; s0.y += v0.y; s0.z += v0.z; s0.w += v0.w;
            s1.x += v1.x; s1.y += v1.y; s1.z += v1.z; s1.w += v1.w;
            s2.x += v2.x; s2.y += v2.y; s2.z += v2.z; s2.w += v2.w;
            s3.x += v3.x; s3.y += v3.y; s3.z += v3.z; s3.w += v3.w;
        }
    }

    float acc[4][7];
#pragma unroll
    for (int cc = 0; cc < 4; cc++)
#pragma unroll
        for (int pw = 0; pw < 7; pw++) acc[cc][pw] = 0.f;

    float sc[4][4] = {{s0.x, s0.y, s0.z, s0.w}, {s1.x, s1.y, s1.z, s1.w},
                      {s2.x, s2.y, s2.z, s2.w}, {s3.x, s3.y, s3.z, s3.w}};
#pragma unroll
    for (int q = 0; q < 4; q++) {
        int b = ya + 4 * lane + q - y0;
        bool valid = (b >= 0) && (b < Wc);
#pragma unroll
        for (int pw = 0; pw < 7; pw++) {
            int ws = (pw * Wc) / 7;
            int we = ((pw + 1) * Wc + 6) / 7;
            if (valid && b >= ws && b < we) {
#pragma unroll
                for (int cc = 0; cc < 4; cc++) acc[cc][pw] += sc[cc][q];
            }
        }
    }

#pragma unroll
    for (int pw = 0; pw < 7; pw++) {
        float v0 = wsum(acc[0][pw]);
        float v1 = wsum(acc[1][pw]);
        float v2 = wsum(acc[2][pw]);
        float v3 = wsum(acc[3][pw]);
        if (lane == 0) {
            int ws = (pw * Wc) / 7;
            int we = ((pw + 1) * Wc + 6) / 7;
            float inv = 1.f / (float)((he - hs) * (we - ws));
            int ob = ((r * 7 + ph) * 7 + pw) * FEAT + c0;
            g_pooled[ob + 0] = v0 * inv;
            g_pooled[ob + 1] = v1 * inv;
            g_pooled[ob + 2] = v2 * inv;
            g_pooled[ob + 3] = v3 * inv;
        }
    }
}

// ---------------- kernel 2: 1x1 conv + bias-seed h1/h2 (R5 exact) ---------
// grid = 64 o-splits * 7 ph = 448 blocks; warp owns 1 o-row; f32x2 FMA.
__global__ __launch_bounds__(256) void conv_kernel(
    const float* __restrict__ conv_w, const float* __restrict__ conv_b,
    const float* __restrict__ d1_b, const float* __restrict__ d2_b) {
    __shared__ float smact[4 * 7 * 256];   // 28 KB  [r][pw][k]

    // fold former init_kernel: seed g_h1/g_h2 with biases (blocks 0..23)
    {
        int gi = blockIdx.x * 256 + threadIdx.x;
        if (gi < H1N) {
            float b = d1_b[gi];
#pragma unroll
            for (int rr = 0; rr < 4; rr++) g_h1[rr * H1N + gi] = b;
        } else if (gi < H1N + H2N) {
            int j = gi - H1N;
            float b = d2_b[j];
#pragma unroll
            for (int rr = 0; rr < 4; rr++) g_h2[rr * H2N + j] = b;
        }
    }

    int ph = blockIdx.x % 7;
    int osplit = blockIdx.x / 7;
    int wid = threadIdx.x >> 5;
    int lane = threadIdx.x & 31;
    int o = osplit * 8 + wid;

    unsigned long long acc2[4][7];
#pragma unroll
    for (int rr = 0; rr < 4; rr++)
#pragma unroll
        for (int pw = 0; pw < 7; pw++) acc2[rr][pw] = 0ull;

    for (int kc = 0; kc < 8; kc++) {
        __syncthreads();
        for (int i = threadIdx.x; i < 1792; i += 256) {
            int rr = i / 448;
            int rem = i - rr * 448;
            int pw = rem / 64;
            int k4 = rem - pw * 64;
            *(float4*)(smact + (rr * 7 + pw) * 256 + k4 * 4) =
                *(const float4*)(g_pooled + (size_t)((rr * 7 + ph) * 7 + pw) * FEAT +
                                 kc * 256 + k4 * 4);
        }
        __syncthreads();
#pragma unroll
        for (int it = 0; it < 2; it++) {
            int k = lane * 4 + it * 128;
            float4 w = *(const float4*)(conv_w + (size_t)o * FEAT + kc * 256 + k);
            unsigned long long wlo, whi;
            PACK2(wlo, w.x, w.y);
            PACK2(whi, w.z, w.w);
#pragma unroll
            for (int rr = 0; rr < 4; rr++) {
#pragma unroll
                for (int pw = 0; pw < 7; pw++) {
                    ulonglong2 f = *(const ulonglong2*)(smact + (rr * 7 + pw) * 256 + k);
                    FMA2(acc2[rr][pw], wlo, f.x);
                    FMA2(acc2[rr][pw], whi, f.y);
                }
            }
        }
    }

    float b = conv_b[o];
#pragma unroll
    for (int rr = 0; rr < 4; rr++) {
#pragma unroll
        for (int pw = 0; pw < 7; pw++) {
            float lo, hi;
            UNPACK2(lo, hi, acc2[rr][pw]);
            float v = wsum(lo + hi);
            if (lane == 0)
                g_flat[(size_t)rr * FLATN + o * 49 + ph * 7 + pw] = v + b;
        }
    }
}

// ---------------- kernel 3: dense1 — K-split 28 (ONLY delta vs R5) --------
// grid = 256 rowblocks * 28 ksplits = 7168 blocks; 896-chunk, 14KB smem;
// each warp owns 2 output rows, weights streamed via __ldcs + f32x2 FMA.
__global__ __launch_bounds__(256) void d1_kernel(const float* __restrict__ d1_w) {
    __shared__ float smf[4 * D1_CHUNK];   // 14 KB
    int ks = blockIdx.x % D1_KSPLIT;
    int rowblk = blockIdx.x / D1_KSPLIT;
    int wid = threadIdx.x >> 5;
    int lane = threadIdx.x & 31;
    int j0 = rowblk * 16 + wid * 2;
    int kb = ks * D1_CHUNK;

    for (int i = threadIdx.x; i < 896; i += 256) {   // 896 float4 = 3584 floats
        int rr = i / 224;
        int k4 = i - rr * 224;
        *(float4*)(smf + rr * D1_CHUNK + k4 * 4) =
            *(const float4*)(g_flat + (size_t)rr * FLATN + kb + k4 * 4);
    }
    __syncthreads();

    unsigned long long a00 = 0, a01 = 0, a02 = 0, a03 = 0;
    unsigned long long a10 = 0, a11 = 0, a12 = 0, a13 = 0;

    const float* wp0 = d1_w + (size_t)(j0 + 0) * FLATN + kb;
    const float* wp1 = d1_w + (size_t)(j0 + 1) * FLATN + kb;
#pragma unroll
    for (int it = 0; it < 7; it++) {
        int k = lane * 4 + it * 128;
        float4 w0 = __ldcs((const float4*)(wp0 + k));
        float4 w1 = __ldcs((const float4*)(wp1 + k));
        unsigned long long w0lo, w0hi, w1lo, w1hi;
        PACK2(w0lo, w0.x, w0.y); PACK2(w0hi, w0.z, w0.w);
        PACK2(w1lo, w1.x, w1.y); PACK2(w1hi, w1.z, w1.w);
        ulonglong2 f0 = *(const ulonglong2*)(smf + 0 * D1_CHUNK + k);
        ulonglong2 f1 = *(const ulonglong2*)(smf + 1 * D1_CHUNK + k);
        ulonglong2 f2 = *(const ulonglong2*)(smf + 2 * D1_CHUNK + k);
        ulonglong2 f3 = *(const ulonglong2*)(smf + 3 * D1_CHUNK + k);
        FMA2(a00, w0lo, f0.x); FMA2(a00, w0hi, f0.y);
        FMA2(a01, w0lo, f1.x); FMA2(a01, w0hi, f1.y);
        FMA2(a02, w0lo, f2.x); FMA2(a02, w0hi, f2.y);
        FMA2(a03, w0lo, f3.x); FMA2(a03, w0hi, f3.y);
        FMA2(a10, w1lo, f0.x); FMA2(a10, w1hi, f0.y);
        FMA2(a11, w1lo, f1.x); FMA2(a11, w1hi, f1.y);
        FMA2(a12, w1lo, f2.x); FMA2(a12, w1hi, f2.y);
        FMA2(a13, w1lo, f3.x); FMA2(a13, w1hi, f3.y);
    }

    float lo, hi, r00, r01, r02, r03, r10, r11, r12, r13;
    UNPACK2(lo, hi, a00); r00 = wsum(lo + hi);
    UNPACK2(lo, hi, a01); r01 = wsum(lo + hi);
    UNPACK2(lo, hi, a02); r02 = wsum(lo + hi);
    UNPACK2(lo, hi, a03); r03 = wsum(lo + hi);
    UNPACK2(lo, hi, a10); r10 = wsum(lo + hi);
    UNPACK2(lo, hi, a11); r11 = wsum(lo + hi);
    UNPACK2(lo, hi, a12); r12 = wsum(lo + hi);
    UNPACK2(lo, hi, a13); r13 = wsum(lo + hi);
    if (lane == 0) {
        atomicAdd(&g_h1[0 * H1N + j0 + 0], r00);
        atomicAdd(&g_h1[1 * H1N + j0 + 0], r01);
        atomicAdd(&g_h1[2 * H1N + j0 + 0], r02);
        atomicAdd(&g_h1[3 * H1N + j0 + 0], r03);
        atomicAdd(&g_h1[0 * H1N + j0 + 1], r10);
        atomicAdd(&g_h1[1 * H1N + j0 + 1], r11);
        atomicAdd(&g_h1[2 * H1N + j0 + 1], r12);
        atomicAdd(&g_h1[3 * H1N + j0 + 1], r13);
    }
}

// ---------------- kernel 4: dense2 (R5 exact: K-split 8, 1024 blocks) -----
__global__ __launch_bounds__(256) void d2_kernel(const float* __restrict__ d2_w) {
    __shared__ float smh[4 * 512];   // 8 KB
    int ks = blockIdx.x & 7;
    int rowblk = blockIdx.x >> 3;
    int wid = threadIdx.x >> 5;
    int lane = threadIdx.x & 31;
    int j0 = rowblk * 16 + wid * 2;
    int kb = ks * 512;

    for (int i = threadIdx.x; i < 512; i += 256) {   // float4 units
        int rr = i >> 7;
        int k4 = i & 127;
        float4 v = *(const float4*)(g_h1 + (size_t)rr * H1N + kb + k4 * 4);
        v.x = fmaxf(v.x, 0.f); v.y = fmaxf(v.y, 0.f);
        v.z = fmaxf(v.z, 0.f); v.w = fmaxf(v.w, 0.f);
        *(float4*)(smh + rr * 512 + k4 * 4) = v;
    }
    __syncthreads();

    unsigned long long a00 = 0, a01 = 0, a02 = 0, a03 = 0;
    unsigned long long a10 = 0, a11 = 0, a12 = 0, a13 = 0;

    const float* wp0 = d2_w + (size_t)(j0 + 0) * H1N + kb;
    const float* wp1 = d2_w + (size_t)(j0 + 1) * H1N + kb;
#pragma unroll
    for (int it = 0; it < 4; it++) {
        int k = lane * 4 + it * 128;
        float4 w0 = __ldcs((const float4*)(wp0 + k));
        float4 w1 = __ldcs((const float4*)(wp1 + k));
        unsigned long long w0lo, w0hi, w1lo, w1hi;
        PACK2(w0lo, w0.x, w0.y); PACK2(w0hi, w0.z, w0.w);
        PACK2(w1lo, w1.x, w1.y); PACK2(w1hi, w1.z, w1.w);
        ulonglong2 f0 = *(const ulonglong2*)(smh + 0 * 512 + k);
        ulonglong2 f1 = *(const ulonglong2*)(smh + 1 * 512 + k);
        ulonglong2 f2 = *(const ulonglong2*)(smh + 2 * 512 + k);
        ulonglong2 f3 = *(const ulonglong2*)(smh + 3 * 512 + k);
        FMA2(a00, w0lo, f0.x); FMA2(a00, w0hi, f0.y);
        FMA2(a01, w0lo, f1.x); FMA2(a01, w0hi, f1.y);
        FMA2(a02, w0lo, f2.x); FMA2(a02, w0hi, f2.y);
        FMA2(a03, w0lo, f3.x); FMA2(a03, w0hi, f3.y);
        FMA2(a10, w1lo, f0.x); FMA2(a10, w1hi, f0.y);
        FMA2(a11, w1lo, f1.x); FMA2(a11, w1hi, f1.y);
        FMA2(a12, w1lo, f2.x); FMA2(a12, w1hi, f2.y);
        FMA2(a13, w1lo, f3.x); FMA2(a13, w1hi, f3.y);
    }

    float lo, hi, r00, r01, r02, r03, r10, r11, r12, r13;
    UNPACK2(lo, hi, a00); r00 = wsum(lo + hi);
    UNPACK2(lo, hi, a01); r01 = wsum(lo + hi);
    UNPACK2(lo, hi, a02); r02 = wsum(lo + hi);
    UNPACK2(lo, hi, a03); r03 = wsum(lo + hi);
    UNPACK2(lo, hi, a10); r10 = wsum(lo + hi);
    UNPACK2(lo, hi, a11); r11 = wsum(lo + hi);
    UNPACK2(lo, hi, a12); r12 = wsum(lo + hi);
    UNPACK2(lo, hi, a13); r13 = wsum(lo + hi);
    if (lane == 0) {
        atomicAdd(&g_h2[0 * H2N + j0 + 0], r00);
        atomicAdd(&g_h2[1 * H2N + j0 + 0], r01);
        atomicAdd(&g_h2[2 * H2N + j0 + 0], r02);
        atomicAdd(&g_h2[3 * H2N + j0 + 0], r03);
        atomicAdd(&g_h2[0 * H2N + j0 + 1], r10);
        atomicAdd(&g_h2[1 * H2N + j0 + 1], r11);
        atomicAdd(&g_h2[2 * H2N + j0 + 1], r12);
        atomicAdd(&g_h2[3 * H2N + j0 + 1], r13);
    }
}

// ---------------- kernel 5: heads (52 blocks, R5 exact) --------------------
// grid = 4 r * 13 rowgroups; 8 warps, one output row each (101 rows total).
__global__ __launch_bounds__(256) void head_kernel(
    const float* __restrict__ d3_w, const float* __restrict__ d4_w,
    float* __restrict__ out) {
    __shared__ float smh[H2N];
    int r = blockIdx.x & 3;
    int grp = blockIdx.x >> 2;
    int wid = threadIdx.x >> 5;
    int lane = threadIdx.x & 31;

    for (int i = threadIdx.x; i < H2N / 4; i += 256) {
        float4 v = *(const float4*)(g_h2 + (size_t)r * H2N + i * 4);
        v.x = fmaxf(v.x, 0.f); v.y = fmaxf(v.y, 0.f);
        v.z = fmaxf(v.z, 0.f); v.w = fmaxf(v.w, 0.f);
        *(float4*)(smh + i * 4) = v;
    }
    __syncthreads();

    int row = grp * 8 + wid;
    if (row >= NCLS + NREG) return;
    const float* wrow = (row < NCLS)
                            ? d3_w + (size_t)row * H2N
                            : d4_w + (size_t)(row - NCLS) * H2N;
    float a = 0.f;
#pragma unroll
    for (int it = 0; it < 16; it++) {
        int k = lane * 4 + it * 128;
        float4 w = __ldcs((const float4*)(wrow + k));
        float4 f = *(const float4*)(smh + k);
        a += w.x * f.x + w.y * f.y + w.z * f.z + w.w * f.w;
    }
    a = wsum(a);
    if (lane == 0) {
        if (row < NCLS) g_logits[r * NCLS + row] = a;
        else out[NROIS * NCLS + r * NREG + (row - NCLS)] = a;
    }
}

// ---------------- kernel 6: softmax over class logits (R5 exact) -----------
__global__ __launch_bounds__(128) void softmax_kernel(float* __restrict__ out) {
    int r = threadIdx.x >> 5;
    int lane = threadIdx.x & 31;
    float v = (lane < NCLS) ? g_logits[r * NCLS + lane] : -INFINITY;
    float m = v;
#pragma unroll
    for (int o = 16; o > 0; o >>= 1)
        m = fmaxf(m, __shfl_xor_sync(0xffffffffu, m, o));
    float e = (lane < NCLS) ? expf(v - m) : 0.f;
    float s = wsum(e);
    if (lane < NCLS) out[r * NCLS + lane] = e / s;
}

// ---------------- launch ---------------------------------------------------
extern "C" void kernel_launch(void* const* d_in, const int* in_sizes, int n_in,
                              void* d_out, int out_size) {
    const float* base_x = (const float*)d_in[0];
    const int*   rois   = (const int*)d_in[1];
    const float* conv_w = (const float*)d_in[2];
    const float* conv_b = (const float*)d_in[3];
    const float* d1_w   = (const float*)d_in[4];
    const float* d1_b   = (const float*)d_in[5];
    const float* d2_w   = (const float*)d_in[6];
    const float* d2_b   = (const float*)d_in[7];
    const float* d3_w   = (const float*)d_in[8];
    const float* d4_w   = (const float*)d_in[9];
    float* out = (float*)d_out;

    pool_kernel<<<NROIS * (FEAT / 4), 224>>>(base_x, rois);
    conv_kernel<<<448, 256>>>(conv_w, conv_b, d1_b, d2_b);
    d1_kernel<<<256 * D1_KSPLIT, 256>>>(d1_w);
    d2_kernel<<<1024, 256>>>(d2_w);
    head_kernel<<<52, 256>>>(d3_w, d4_w, out);
    softmax_kernel<<<1, 128>>>(out);
}

// round 12
// speedup vs baseline: 1.2551x; 1.0486x over previous
#include <cuda_runtime.h>
#include <math.h>

#define POOLN 7
#define NROIS 4
#define FEAT 2048
#define RED 512
#define FLATN (RED * 49)      // 25088 = 14 * 1792
#define H1N 4096
#define H2N 2048
#define NCLS 21
#define NREG 80
#define IMG 128

#define D1_CHUNK 1792
#define D1_KSPLIT 14          // 14 splits * 1792 = 25088

// packed f32x2 helpers (FFMA2 path — PTX-only)
#define PACK2(u, a, b) asm("mov.b64 %0, {%1, %2};" : "=l"(u) : "f"(a), "f"(b))
#define FMA2(acc, u, v) \
    asm("fma.rn.f32x2 %0, %1, %2, %0;" : "+l"(acc) : "l"(u), "l"(v))
#define UNPACK2(a, b, u) asm("mov.b64 {%0, %1}, %2;" : "=f"(a), "=f"(b) : "l"(u))

// ---------------- scratch (device globals; no allocations allowed) -------
__device__ float g_pooled[NROIS * 49 * FEAT];   // [r*49+hw][c]  c fastest
__device__ float g_flat[NROIS * FLATN];         // [r][o*49 + hw]
__device__ float g_h1[NROIS * H1N];             // pre-relu, bias-seeded
__device__ float g_h2[NROIS * H2N];             // pre-relu, bias-seeded
__device__ float g_logits[NROIS * NCLS];

__device__ __forceinline__ float wsum(float v) {
#pragma unroll
    for (int o = 16; o > 0; o >>= 1) v += __shfl_xor_sync(0xffffffffu, v, o);
    return v;
}

// ---------------- kernel 1: ROI adaptive avg pool (R5 exact) --------------
// 4 channels / block, float4 column loads. grid = 4r * 512 = 2048 blocks.
__global__ __launch_bounds__(224) void pool_kernel(
    const float* __restrict__ x, const int* __restrict__ rois) {
    int blk = blockIdx.x;
    int r = blk & 3;
    int c0 = (blk >> 2) * 4;
    int wid = threadIdx.x >> 5;
    int lane = threadIdx.x & 31;

    int x0 = rois[r * 4 + 0];
    int y0 = rois[r * 4 + 1];
    int Wc = rois[r * 4 + 2];   // cols count (axis2 = y:y+h)
    int Hc = rois[r * 4 + 3];   // rows count (axis1 = x:x+w)

    int ph = wid;
    int hs = (ph * Hc) / 7;
    int he = ((ph + 1) * Hc + 6) / 7;

    int ya = y0 & ~3;
    int nl = (y0 + Wc - ya + 3) >> 2;
    int nlmax = (IMG - ya) >> 2;
    if (nl > nlmax) nl = nlmax;

    float4 s0 = {0,0,0,0}, s1 = {0,0,0,0}, s2 = {0,0,0,0}, s3 = {0,0,0,0};

    if (lane < nl) {
        const float* pl0 = x + (size_t)(c0 + 0) * (IMG * IMG) +
                           (size_t)x0 * IMG + ya + 4 * lane;
        const float* pl1 = pl0 + IMG * IMG;
        const float* pl2 = pl1 + IMG * IMG;
        const float* pl3 = pl2 + IMG * IMG;
        int a = hs;
        for (; a + 1 < he; a += 2) {
            float4 v00 = *(const float4*)(pl0 + (a + 0) * IMG);
            float4 v10 = *(const float4*)(pl1 + (a + 0) * IMG);
            float4 v20 = *(const float4*)(pl2 + (a + 0) * IMG);
            float4 v30 = *(const float4*)(pl3 + (a + 0) * IMG);
            float4 v01 = *(const float4*)(pl0 + (a + 1) * IMG);
            float4 v11 = *(const float4*)(pl1 + (a + 1) * IMG);
            float4 v21 = *(const float4*)(pl2 + (a + 1) * IMG);
            float4 v31 = *(const float4*)(pl3 + (a + 1) * IMG);
            s0.x += v00.x + v01.x; s0.y += v00.y + v01.y;
            s0.z += v00.z + v01.z; s0.w += v00.w + v01.w;
            s1.x += v10.x + v11.x; s1.y += v10.y + v11.y;
            s1.z += v10.z + v11.z; s1.w += v10.w + v11.w;
            s2.x += v20.x + v21.x; s2.y += v20.y + v21.y;
            s2.z += v20.z + v21.z; s2.w += v20.w + v21.w;
            s3.x += v30.x + v31.x; s3.y += v30.y + v31.y;
            s3.z += v30.z + v31.z; s3.w += v30.w + v31.w;
        }
        if (a < he) {
            float4 v0 = *(const float4*)(pl0 + a * IMG);
            float4 v1 = *(const float4*)(pl1 + a * IMG);
            float4 v2 = *(const float4*)(pl2 + a * IMG);
            float4 v3 = *(const float4*)(pl3 + a * IMG);
            s0.x += v0.x; s0.y += v0.y; s0.z += v0.z; s0.w += v0.w;
            s1.x += v1.x; s1.y += v1.y; s1.z += v1.z; s1.w += v1.w;
            s2.x += v2.x; s2.y += v2.y; s2.z += v2.z; s2.w += v2.w;
            s3.x += v3.x; s3.y += v3.y; s3.z += v3.z; s3.w += v3.w;
        }
    }

    float acc[4][7];
#pragma unroll
    for (int cc = 0; cc < 4; cc++)
#pragma unroll
        for (int pw = 0; pw < 7; pw++) acc[cc][pw] = 0.f;

    float sc[4][4] = {{s0.x, s0.y, s0.z, s0.w}, {s1.x, s1.y, s1.z, s1.w},
                      {s2.x, s2.y, s2.z, s2.w}, {s3.x, s3.y, s3.z, s3.w}};
#pragma unroll
    for (int q = 0; q < 4; q++) {
        int b = ya + 4 * lane + q - y0;
        bool valid = (b >= 0) && (b < Wc);
#pragma unroll
        for (int pw = 0; pw < 7; pw++) {
            int ws = (pw * Wc) / 7;
            int we = ((pw + 1) * Wc + 6) / 7;
            if (valid && b >= ws && b < we) {
#pragma unroll
                for (int cc = 0; cc < 4; cc++) acc[cc][pw] += sc[cc][q];
            }
        }
    }

#pragma unroll
    for (int pw = 0; pw < 7; pw++) {
        float v0 = wsum(acc[0][pw]);
        float v1 = wsum(acc[1][pw]);
        float v2 = wsum(acc[2][pw]);
        float v3 = wsum(acc[3][pw]);
        if (lane == 0) {
            int ws = (pw * Wc) / 7;
            int we = ((pw + 1) * Wc + 6) / 7;
            float inv = 1.f / (float)((he - hs) * (we - ws));
            int ob = ((r * 7 + ph) * 7 + pw) * FEAT + c0;
            g_pooled[ob + 0] = v0 * inv;
            g_pooled[ob + 1] = v1 * inv;
            g_pooled[ob + 2] = v2 * inv;
            g_pooled[ob + 3] = v3 * inv;
        }
    }
}

// ---------------- kernel 2: 1x1 conv + bias-seed h1/h2 (R5 exact) ---------
// grid = 64 o-splits * 7 ph = 448 blocks; warp owns 1 o-row; f32x2 FMA.
__global__ __launch_bounds__(256) void conv_kernel(
    const float* __restrict__ conv_w, const float* __restrict__ conv_b,
    const float* __restrict__ d1_b, const float* __restrict__ d2_b) {
    __shared__ float smact[4 * 7 * 256];   // 28 KB  [r][pw][k]

    // fold former init_kernel: seed g_h1/g_h2 with biases (blocks 0..23)
    {
        int gi = blockIdx.x * 256 + threadIdx.x;
        if (gi < H1N) {
            float b = d1_b[gi];
#pragma unroll
            for (int rr = 0; rr < 4; rr++) g_h1[rr * H1N + gi] = b;
        } else if (gi < H1N + H2N) {
            int j = gi - H1N;
            float b = d2_b[j];
#pragma unroll
            for (int rr = 0; rr < 4; rr++) g_h2[rr * H2N + j] = b;
        }
    }

    int ph = blockIdx.x % 7;
    int osplit = blockIdx.x / 7;
    int wid = threadIdx.x >> 5;
    int lane = threadIdx.x & 31;
    int o = osplit * 8 + wid;

    unsigned long long acc2[4][7];
#pragma unroll
    for (int rr = 0; rr < 4; rr++)
#pragma unroll
        for (int pw = 0; pw < 7; pw++) acc2[rr][pw] = 0ull;

    for (int kc = 0; kc < 8; kc++) {
        __syncthreads();
        for (int i = threadIdx.x; i < 1792; i += 256) {
            int rr = i / 448;
            int rem = i - rr * 448;
            int pw = rem / 64;
            int k4 = rem - pw * 64;
            *(float4*)(smact + (rr * 7 + pw) * 256 + k4 * 4) =
                *(const float4*)(g_pooled + (size_t)((rr * 7 + ph) * 7 + pw) * FEAT +
                                 kc * 256 + k4 * 4);
        }
        __syncthreads();
#pragma unroll
        for (int it = 0; it < 2; it++) {
            int k = lane * 4 + it * 128;
            float4 w = *(const float4*)(conv_w + (size_t)o * FEAT + kc * 256 + k);
            unsigned long long wlo, whi;
            PACK2(wlo, w.x, w.y);
            PACK2(whi, w.z, w.w);
#pragma unroll
            for (int rr = 0; rr < 4; rr++) {
#pragma unroll
                for (int pw = 0; pw < 7; pw++) {
                    ulonglong2 f = *(const ulonglong2*)(smact + (rr * 7 + pw) * 256 + k);
                    FMA2(acc2[rr][pw], wlo, f.x);
                    FMA2(acc2[rr][pw], whi, f.y);
                }
            }
        }
    }

    float b = conv_b[o];
#pragma unroll
    for (int rr = 0; rr < 4; rr++) {
#pragma unroll
        for (int pw = 0; pw < 7; pw++) {
            float lo, hi;
            UNPACK2(lo, hi, acc2[rr][pw]);
            float v = wsum(lo + hi);
            if (lane == 0)
                g_flat[(size_t)rr * FLATN + o * 49 + ph * 7 + pw] = v + b;
        }
    }
}

// ---------------- kernel 3: dense1 — smem-FREE (ONLY delta vs R5) ---------
// grid = 256 rowblocks * 14 ksplits = 3584 blocks. Activations read directly
// from g_flat: the 28KB chunk per ksplit is shared by all warps/blocks on an
// SM and L1-resident (weights use __ldcs streaming so they evict first).
// Removes smem fill + both __syncthreads per block.
__global__ __launch_bounds__(256) void d1_kernel(const float* __restrict__ d1_w) {
    int ks = blockIdx.x % D1_KSPLIT;
    int rowblk = blockIdx.x / D1_KSPLIT;
    int wid = threadIdx.x >> 5;
    int lane = threadIdx.x & 31;
    int j0 = rowblk * 16 + wid * 2;
    int kb = ks * D1_CHUNK;

    unsigned long long a00 = 0, a01 = 0, a02 = 0, a03 = 0;
    unsigned long long a10 = 0, a11 = 0, a12 = 0, a13 = 0;

    const float* wp0 = d1_w + (size_t)(j0 + 0) * FLATN + kb;
    const float* wp1 = d1_w + (size_t)(j0 + 1) * FLATN + kb;
    const float* f0p = g_flat + (size_t)0 * FLATN + kb;
    const float* f1p = g_flat + (size_t)1 * FLATN + kb;
    const float* f2p = g_flat + (size_t)2 * FLATN + kb;
    const float* f3p = g_flat + (size_t)3 * FLATN + kb;
#pragma unroll
    for (int it = 0; it < 14; it++) {
        int k = lane * 4 + it * 128;
        float4 w0 = __ldcs((const float4*)(wp0 + k));
        float4 w1 = __ldcs((const float4*)(wp1 + k));
        unsigned long long w0lo, w0hi, w1lo, w1hi;
        PACK2(w0lo, w0.x, w0.y); PACK2(w0hi, w0.z, w0.w);
        PACK2(w1lo, w1.x, w1.y); PACK2(w1hi, w1.z, w1.w);
        ulonglong2 f0 = *(const ulonglong2*)(f0p + k);
        ulonglong2 f1 = *(const ulonglong2*)(f1p + k);
        ulonglong2 f2 = *(const ulonglong2*)(f2p + k);
        ulonglong2 f3 = *(const ulonglong2*)(f3p + k);
        FMA2(a00, w0lo, f0.x); FMA2(a00, w0hi, f0.y);
        FMA2(a01, w0lo, f1.x); FMA2(a01, w0hi, f1.y);
        FMA2(a02, w0lo, f2.x); FMA2(a02, w0hi, f2.y);
        FMA2(a03, w0lo, f3.x); FMA2(a03, w0hi, f3.y);
        FMA2(a10, w1lo, f0.x); FMA2(a10, w1hi, f0.y);
        FMA2(a11, w1lo, f1.x); FMA2(a11, w1hi, f1.y);
        FMA2(a12, w1lo, f2.x); FMA2(a12, w1hi, f2.y);
        FMA2(a13, w1lo, f3.x); FMA2(a13, w1hi, f3.y);
    }

    float lo, hi, r00, r01, r02, r03, r10, r11, r12, r13;
    UNPACK2(lo, hi, a00); r00 = wsum(lo + hi);
    UNPACK2(lo, hi, a01); r01 = wsum(lo + hi);
    UNPACK2(lo, hi, a02); r02 = wsum(lo + hi);
    UNPACK2(lo, hi, a03); r03 = wsum(lo + hi);
    UNPACK2(lo, hi, a10); r10 = wsum(lo + hi);
    UNPACK2(lo, hi, a11); r11 = wsum(lo + hi);
    UNPACK2(lo, hi, a12); r12 = wsum(lo + hi);
    UNPACK2(lo, hi, a13); r13 = wsum(lo + hi);
    if (lane == 0) {
        atomicAdd(&g_h1[0 * H1N + j0 + 0], r00);
        atomicAdd(&g_h1[1 * H1N + j0 + 0], r01);
        atomicAdd(&g_h1[2 * H1N + j0 + 0], r02);
        atomicAdd(&g_h1[3 * H1N + j0 + 0], r03);
        atomicAdd(&g_h1[0 * H1N + j0 + 1], r10);
        atomicAdd(&g_h1[1 * H1N + j0 + 1], r11);
        atomicAdd(&g_h1[2 * H1N + j0 + 1], r12);
        atomicAdd(&g_h1[3 * H1N + j0 + 1], r13);
    }
}

// ---------------- kernel 4: dense2 (R5 exact: K-split 8, 1024 blocks) -----
__global__ __launch_bounds__(256) void d2_kernel(const float* __restrict__ d2_w) {
    __shared__ float smh[4 * 512];   // 8 KB
    int ks = blockIdx.x & 7;
    int rowblk = blockIdx.x >> 3;
    int wid = threadIdx.x >> 5;
    int lane = threadIdx.x & 31;
    int j0 = rowblk * 16 + wid * 2;
    int kb = ks * 512;

    for (int i = threadIdx.x; i < 512; i += 256) {   // float4 units
        int rr = i >> 7;
        int k4 = i & 127;
        float4 v = *(const float4*)(g_h1 + (size_t)rr * H1N + kb + k4 * 4);
        v.x = fmaxf(v.x, 0.f); v.y = fmaxf(v.y, 0.f);
        v.z = fmaxf(v.z, 0.f); v.w = fmaxf(v.w, 0.f);
        *(float4*)(smh + rr * 512 + k4 * 4) = v;
    }
    __syncthreads();

    unsigned long long a00 = 0, a01 = 0, a02 = 0, a03 = 0;
    unsigned long long a10 = 0, a11 = 0, a12 = 0, a13 = 0;

    const float* wp0 = d2_w + (size_t)(j0 + 0) * H1N + kb;
    const float* wp1 = d2_w + (size_t)(j0 + 1) * H1N + kb;
#pragma unroll
    for (int it = 0; it < 4; it++) {
        int k = lane * 4 + it * 128;
        float4 w0 = __ldcs((const float4*)(wp0 + k));
        float4 w1 = __ldcs((const float4*)(wp1 + k));
        unsigned long long w0lo, w0hi, w1lo, w1hi;
        PACK2(w0lo, w0.x, w0.y); PACK2(w0hi, w0.z, w0.w);
        PACK2(w1lo, w1.x, w1.y); PACK2(w1hi, w1.z, w1.w);
        ulonglong2 f0 = *(const ulonglong2*)(smh + 0 * 512 + k);
        ulonglong2 f1 = *(const ulonglong2*)(smh + 1 * 512 + k);
        ulonglong2 f2 = *(const ulonglong2*)(smh + 2 * 512 + k);
        ulonglong2 f3 = *(const ulonglong2*)(smh + 3 * 512 + k);
        FMA2(a00, w0lo, f0.x); FMA2(a00, w0hi, f0.y);
        FMA2(a01, w0lo, f1.x); FMA2(a01, w0hi, f1.y);
        FMA2(a02, w0lo, f2.x); FMA2(a02, w0hi, f2.y);
        FMA2(a03, w0lo, f3.x); FMA2(a03, w0hi, f3.y);
        FMA2(a10, w1lo, f0.x); FMA2(a10, w1hi, f0.y);
        FMA2(a11, w1lo, f1.x); FMA2(a11, w1hi, f1.y);
        FMA2(a12, w1lo, f2.x); FMA2(a12, w1hi, f2.y);
        FMA2(a13, w1lo, f3.x); FMA2(a13, w1hi, f3.y);
    }

    float lo, hi, r00, r01, r02, r03, r10, r11, r12, r13;
    UNPACK2(lo, hi, a00); r00 = wsum(lo + hi);
    UNPACK2(lo, hi, a01); r01 = wsum(lo + hi);
    UNPACK2(lo, hi, a02); r02 = wsum(lo + hi);
    UNPACK2(lo, hi, a03); r03 = wsum(lo + hi);
    UNPACK2(lo, hi, a10); r10 = wsum(lo + hi);
    UNPACK2(lo, hi, a11); r11 = wsum(lo + hi);
    UNPACK2(lo, hi, a12); r12 = wsum(lo + hi);
    UNPACK2(lo, hi, a13); r13 = wsum(lo + hi);
    if (lane == 0) {
        atomicAdd(&g_h2[0 * H2N + j0 + 0], r00);
        atomicAdd(&g_h2[1 * H2N + j0 + 0], r01);
        atomicAdd(&g_h2[2 * H2N + j0 + 0], r02);
        atomicAdd(&g_h2[3 * H2N + j0 + 0], r03);
        atomicAdd(&g_h2[0 * H2N + j0 + 1], r10);
        atomicAdd(&g_h2[1 * H2N + j0 + 1], r11);
        atomicAdd(&g_h2[2 * H2N + j0 + 1], r12);
        atomicAdd(&g_h2[3 * H2N + j0 + 1], r13);
    }
}

// ---------------- kernel 5: heads (52 blocks, R5 exact) --------------------
// grid = 4 r * 13 rowgroups; 8 warps, one output row each (101 rows total).
__global__ __launch_bounds__(256) void head_kernel(
    const float* __restrict__ d3_w, const float* __restrict__ d4_w,
    float* __restrict__ out) {
    __shared__ float smh[H2N];
    int r = blockIdx.x & 3;
    int grp = blockIdx.x >> 2;
    int wid = threadIdx.x >> 5;
    int lane = threadIdx.x & 31;

    for (int i = threadIdx.x; i < H2N / 4; i += 256) {
        float4 v = *(const float4*)(g_h2 + (size_t)r * H2N + i * 4);
        v.x = fmaxf(v.x, 0.f); v.y = fmaxf(v.y, 0.f);
        v.z = fmaxf(v.z, 0.f); v.w = fmaxf(v.w, 0.f);
        *(float4*)(smh + i * 4) = v;
    }
    __syncthreads();

    int row = grp * 8 + wid;
    if (row >= NCLS + NREG) return;
    const float* wrow = (row < NCLS)
                            ? d3_w + (size_t)row * H2N
                            : d4_w + (size_t)(row - NCLS) * H2N;
    float a = 0.f;
#pragma unroll
    for (int it = 0; it < 16; it++) {
        int k = lane * 4 + it * 128;
        float4 w = __ldcs((const float4*)(wrow + k));
        float4 f = *(const float4*)(smh + k);
        a += w.x * f.x + w.y * f.y + w.z * f.z + w.w * f.w;
    }
    a = wsum(a);
    if (lane == 0) {
        if (row < NCLS) g_logits[r * NCLS + row] = a;
        else out[NROIS * NCLS + r * NREG + (row - NCLS)] = a;
    }
}

// ---------------- kernel 6: softmax over class logits (R5 exact) -----------
__global__ __launch_bounds__(128) void softmax_kernel(float* __restrict__ out) {
    int r = threadIdx.x >> 5;
    int lane = threadIdx.x & 31;
    float v = (lane < NCLS) ? g_logits[r * NCLS + lane] : -INFINITY;
    float m = v;
#pragma unroll
    for (int o = 16; o > 0; o >>= 1)
        m = fmaxf(m, __shfl_xor_sync(0xffffffffu, m, o));
    float e = (lane < NCLS) ? expf(v - m) : 0.f;
    float s = wsum(e);
    if (lane < NCLS) out[r * NCLS + lane] = e / s;
}

// ---------------- launch ---------------------------------------------------
extern "C" void kernel_launch(void* const* d_in, const int* in_sizes, int n_in,
                              void* d_out, int out_size) {
    const float* base_x = (const float*)d_in[0];
    const int*   rois   = (const int*)d_in[1];
    const float* conv_w = (const float*)d_in[2];
    const float* conv_b = (const float*)d_in[3];
    const float* d1_w   = (const float*)d_in[4];
    const float* d1_b   = (const float*)d_in[5];
    const float* d2_w   = (const float*)d_in[6];
    const float* d2_b   = (const float*)d_in[7];
    const float* d3_w   = (const float*)d_in[8];
    const float* d4_w   = (const float*)d_in[9];
    float* out = (float*)d_out;

    pool_kernel<<<NROIS * (FEAT / 4), 224>>>(base_x, rois);
    conv_kernel<<<448, 256>>>(conv_w, conv_b, d1_b, d2_b);
    d1_kernel<<<256 * D1_KSPLIT, 256>>>(d1_w);
    d2_kernel<<<1024, 256>>>(d2_w);
    head_kernel<<<52, 256>>>(d3_w, d4_w, out);
    softmax_kernel<<<1, 128>>>(out);
}